// round 1
// baseline (speedup 1.0000x reference)
#include <cuda_runtime.h>
#include <cuda_bf16.h>
#include <cstdint>

#define NS 7
#define NR 6
#define SR 42          // NS * NR
#define TPB 128

// sqrt((2l+1)/(4*pi)) for l = 0..6
__device__ __constant__ float kCoef[7] = {
    0.28209479177387814f,
    0.48860251190291992f,
    0.63078313050504009f,
    0.74635266518023078f,
    0.84628437532163443f,
    0.93560257962738882f,
    1.01710723628205458f
};

__global__ void __launch_bounds__(TPB)
dime_sbf_kernel(const float* __restrict__ o,
                const float* __restrict__ rbf,
                const void*  __restrict__ src_v,
                const void*  __restrict__ dst_v,
                float* __restrict__ out,
                long long E, long long T)
{
    __shared__ float cbf_sh[TPB][8];   // padded to 8 to de-conflict banks
    __shared__ int   src_sh[TPB];      // E = 1e6 fits in int32

    const int tid = threadIdx.x;
    const long long base = (long long)blockIdx.x * TPB;
    const long long t = base + tid;

    // ---- index dtype detection (int64 requested, JAX may demote to int32) ----
    const long long* s64 = (const long long*)src_v;
    const int*       s32 = (const int*)src_v;
    const long long* d64 = (const long long*)dst_v;
    const int*       d32 = (const int*)dst_v;
    bool is64 = true;
    #pragma unroll
    for (int k = 0; k < 4; k++) {
        long long v = __ldg(&s64[k]);
        if (v < 0 || v >= E) is64 = false;
    }

    // ---- phase 1: per-triplet spherical basis into shared ----
    if (t < T) {
        long long si, di;
        if (is64) { si = __ldg(&s64[t]); di = __ldg(&d64[t]); }
        else      { si = (long long)__ldg(&s32[t]); di = (long long)__ldg(&d32[t]); }

        const float* p1 = o + si * 3;
        const float* p2 = o + di * 3;
        float ax = __ldg(p1 + 0), ay = __ldg(p1 + 1), az = __ldg(p1 + 2);
        float bx = __ldg(p2 + 0), by = __ldg(p2 + 1), bz = __ldg(p2 + 2);

        float dot = ax*bx + ay*by + az*bz;
        float n1  = ax*ax + ay*ay + az*az;
        float n2  = bx*bx + by*by + bz*bz;
        // cos(atan2(||cross||, dot)) == dot / (|R1||R2|)
        float c = dot * rsqrtf(n1 * n2);

        float p_prev = 1.0f;   // P_0
        float p_curr = c;      // P_1
        cbf_sh[tid][0] = kCoef[0];
        cbf_sh[tid][1] = kCoef[1] * c;
        #pragma unroll
        for (int l = 2; l < NS; l++) {
            float p = ((float)(2*l - 1) * c * p_curr - (float)(l - 1) * p_prev)
                      * (1.0f / (float)l);
            p_prev = p_curr;
            p_curr = p;
            cbf_sh[tid][l] = kCoef[l] * p;
        }
        src_sh[tid] = (int)si;
    } else {
        #pragma unroll
        for (int l = 0; l < NS; l++) cbf_sh[tid][l] = 0.0f;
        src_sh[tid] = 0;
    }
    __syncthreads();

    // ---- phase 2: cooperative coalesced emission of the 128x42 tile ----
    float* out_blk = out + base * SR;
    const long long rem = T - base;

    if (rem >= TPB) {
        // full tile: flat float4 stores; tile base offset = blockIdx*21504 B (16B aligned)
        const int n4 = TPB * SR / 4;   // 1344
        for (int i4 = tid; i4 < n4; i4 += TPB) {
            float4 v;
            #pragma unroll
            for (int k = 0; k < 4; k++) {
                int e  = i4 * 4 + k;
                int tl = e / SR;           // mul-shift, const divisor
                int j  = e - tl * SR;
                int s  = j / NR;
                float r = __ldg(&rbf[(long long)src_sh[tl] * SR + j]);
                ((float*)&v)[k] = r * cbf_sh[tl][s];
            }
            ((float4*)out_blk)[i4] = v;
        }
    } else {
        // tail block: scalar with bounds
        int ne = (int)rem * SR;
        for (int e = tid; e < ne; e += TPB) {
            int tl = e / SR;
            int j  = e - tl * SR;
            int s  = j / NR;
            out_blk[e] = __ldg(&rbf[(long long)src_sh[tl] * SR + j]) * cbf_sh[tl][s];
        }
    }
}

extern "C" void kernel_launch(void* const* d_in, const int* in_sizes, int n_in,
                              void* d_out, int out_size)
{
    const float* o   = (const float*)d_in[0];    // [E, 3]
    const float* rbf = (const float*)d_in[1];    // [E, 42]
    const void*  src = d_in[2];                  // [T] int64 (or demoted int32)
    const void*  dst = d_in[3];                  // [T]
    float* out = (float*)d_out;                  // [T, 42]

    const long long E = (long long)in_sizes[0] / 3;
    const long long T = (long long)in_sizes[2];

    const int blocks = (int)((T + TPB - 1) / TPB);
    dime_sbf_kernel<<<blocks, TPB>>>(o, rbf, src, dst, out, E, T);
}